// round 14
// baseline (speedup 1.0000x reference)
#include <cuda_runtime.h>
#include <cstdint>

// Problem constants
#define Bv 8
#define Vv 256
#define Hv 128
#define ROWS (Bv*Vv)          // 2048
#define H4 (Hv/4)             // 32 float4 per row

typedef unsigned long long ull;

// Intermediates (device globals; no allocation allowed)
__device__ float g_h0[ROWS*Hv];                 // silu(h @ W_pre + b_pre)
__device__ float g_sk[ROWS*Hv];                 // silu(h @ W_skip + b_skip)
__device__ float g_part[2*ROWS*Hv];             // neigh partial maxes (2 j-halves)

__device__ __forceinline__ float silu_f(float x) {
    return x * (1.0f / (1.0f + __expf(-x)));
}

__device__ __forceinline__ void cp16(uint32_t dst, const void* src) {
    asm volatile("cp.async.cg.shared.global [%0], [%1], 16;" :: "r"(dst), "l"(src));
}
__device__ __forceinline__ void cp_commit() {
    asm volatile("cp.async.commit_group;");
}

__device__ __forceinline__ ull ffma2(ull a, ull b, ull c) {
    ull d;
    asm("fma.rn.f32x2 %0, %1, %2, %3;" : "=l"(d) : "l"(a), "l"(b), "l"(c));
    return d;
}
__device__ __forceinline__ ull pack2(float x, float y) {
    ull d; asm("mov.b64 %0, {%1, %2};" : "=l"(d) : "f"(x), "f"(y)); return d;
}
__device__ __forceinline__ float2 unpack2(ull v) {
    float2 r; asm("mov.b64 {%0, %1}, %2;" : "=f"(r.x), "=f"(r.y) : "l"(v)); return r;
}

// ---------------------------------------------------------------------------
// No-op kernel: keeps ncu's sampled launch on post_kernel (evidence slot).
// ---------------------------------------------------------------------------
__global__ void nop_kernel() {}

// ---------------------------------------------------------------------------
// Kernel A: h0 = silu(h @ W_pre + b_pre), sk = silu(h @ W_skip + b_skip)
// 2-D tiled: 512 blocks (128 row-tiles x 4 col-tiles) x 128 threads.
// v2: W stored in smem as k-PAIRS ([k2][col][2]) so one LDS.64 gives two
// k-weights; inner loop processes 2 k's with 8 independent FFMA2 chains
// (A/B matrix x even/odd k x row-pair). Even/odd partials summed at end.
// ---------------------------------------------------------------------------
__global__ void __launch_bounds__(128) pre_kernel(
    const float* __restrict__ h,
    const float* __restrict__ Wpre,  const float* __restrict__ bpre,
    const float* __restrict__ Wskip, const float* __restrict__ bskip)
{
    __shared__ __align__(16) float sWA[Hv * 32];  // pair layout: [(k>>1)][c][k&1]
    __shared__ __align__(16) float sWB[Hv * 32];
    __shared__ __align__(16) float hT[Hv * 16];   // hT[k][r]

    const int tid  = threadIdx.x;
    const int c    = tid & 31;
    const int rg   = tid >> 5;           // 0..3 (4-row group)
    const int rowT = blockIdx.x >> 2;
    const int colT = blockIdx.x & 3;
    const int row0 = rowT * 16;
    const int col0 = colT * 32;

    // Stage W slices into pair layout: 8 LDG.128/thread/matrix, scatter stores.
    const float4* WAg = (const float4*)Wpre;
    const float4* WBg = (const float4*)Wskip;
#pragma unroll
    for (int r = 0; r < 8; r++) {
        const int x  = r * 128 + tid;          // x = k*8 + c4
        const int k  = x >> 3;
        const int c4 = x & 7;
        float4 va = WAg[k * 32 + colT * 8 + c4];
        float4 vb = WBg[k * 32 + colT * 8 + c4];
        const int base = (k >> 1) * 64 + (k & 1);
        sWA[base + 2 * (c4 * 4 + 0)] = va.x;
        sWA[base + 2 * (c4 * 4 + 1)] = va.y;
        sWA[base + 2 * (c4 * 4 + 2)] = va.z;
        sWA[base + 2 * (c4 * 4 + 3)] = va.w;
        sWB[base + 2 * (c4 * 4 + 0)] = vb.x;
        sWB[base + 2 * (c4 * 4 + 1)] = vb.y;
        sWB[base + 2 * (c4 * 4 + 2)] = vb.z;
        sWB[base + 2 * (c4 * 4 + 3)] = vb.w;
    }

    // Stage transposed h rows: 16 rows x 32 float4 = 512, 4/thread.
    const float4* h4 = (const float4*)h;
#pragma unroll
    for (int x = tid; x < 512; x += 128) {
        const int rr = x & 15, k4 = x >> 4;
        float4 v = h4[(row0 + rr) * H4 + k4];
        hT[(k4 * 4 + 0) * 16 + rr] = v.x;
        hT[(k4 * 4 + 1) * 16 + rr] = v.y;
        hT[(k4 * 4 + 2) * 16 + rr] = v.z;
        hT[(k4 * 4 + 3) * 16 + rr] = v.w;
    }
    __syncthreads();

    ull aA0, aA1, aA2, aA3, aB0, aB1, aB2, aB3;
    {
        const float bA = bpre[col0 + c], bB = bskip[col0 + c];
        aA0 = pack2(bA, bA); aA1 = aA0; aA2 = 0ull; aA3 = 0ull;
        aB0 = pack2(bB, bB); aB1 = aB0; aB2 = 0ull; aB3 = 0ull;
    }

#pragma unroll 8
    for (int k2 = 0; k2 < Hv / 2; k2++) {
        float2 wa = *(const float2*)&sWA[k2 * 64 + 2 * c];
        float2 wb = *(const float2*)&sWB[k2 * 64 + 2 * c];
        ulonglong2 h0 = *(const ulonglong2*)&hT[(2 * k2) * 16 + 4 * rg];
        ulonglong2 h1 = *(const ulonglong2*)&hT[(2 * k2 + 1) * 16 + 4 * rg];
        const ull wa0 = pack2(wa.x, wa.x), wa1 = pack2(wa.y, wa.y);
        const ull wb0 = pack2(wb.x, wb.x), wb1 = pack2(wb.y, wb.y);
        aA0 = ffma2(h0.x, wa0, aA0);
        aA1 = ffma2(h0.y, wa0, aA1);
        aA2 = ffma2(h1.x, wa1, aA2);
        aA3 = ffma2(h1.y, wa1, aA3);
        aB0 = ffma2(h0.x, wb0, aB0);
        aB1 = ffma2(h0.y, wb0, aB1);
        aB2 = ffma2(h1.x, wb1, aB2);
        aB3 = ffma2(h1.y, wb1, aB3);
    }

    {
        float2 a0 = unpack2(aA0), a1 = unpack2(aA1);
        float2 a2 = unpack2(aA2), a3 = unpack2(aA3);
        float2 b0 = unpack2(aB0), b1 = unpack2(aB1);
        float2 b2 = unpack2(aB2), b3 = unpack2(aB3);
        const int row = row0 + 4 * rg;
        const int col = col0 + c;
        g_h0[(row + 0) * Hv + col] = silu_f(a0.x + a2.x);
        g_h0[(row + 1) * Hv + col] = silu_f(a0.y + a2.y);
        g_h0[(row + 2) * Hv + col] = silu_f(a1.x + a3.x);
        g_h0[(row + 3) * Hv + col] = silu_f(a1.y + a3.y);
        g_sk[(row + 0) * Hv + col] = silu_f(b0.x + b2.x);
        g_sk[(row + 1) * Hv + col] = silu_f(b0.y + b2.y);
        g_sk[(row + 2) * Hv + col] = silu_f(b1.x + b3.x);
        g_sk[(row + 3) * Hv + col] = silu_f(b1.y + b3.y);
    }
}

// ---------------------------------------------------------------------------
// Kernel B (dominant): partial neigh max over a 128-wide j-half. (frozen R12)
// ---------------------------------------------------------------------------
__global__ void __launch_bounds__(256) agg_kernel(
    const float* __restrict__ e,
    const int*   __restrict__ graph)
{
    __shared__ float4 h0s[64 * H4];      // 32 KB : h0s[jj][hq], jj in [0,64)
    __shared__ int    jl0[8][64];        // 2 KB  : unmasked j in [0,64)
    __shared__ int    jl1[8][64];        // 2 KB  : unmasked j in [64,128)

    const int tid  = threadIdx.x;
    const int hq   = tid & 31;           // float4 index in H == lane
    const int isub = tid >> 5;           // 0..7 == warp index
    const int b    = blockIdx.x >> 6;
    const int rem  = blockIdx.x & 63;
    const int i0   = (rem >> 1) * 8;
    const int jh   = rem & 1;
    const int j0   = jh * 128;
    const int i    = i0 + isub;

    const float4* H0 = (const float4*)g_h0 + (b * Vv + j0) * H4;
    const uint32_t sb = (uint32_t)__cvta_generic_to_shared(&h0s[0]);

#pragma unroll
    for (int r = 0; r < 8; r++) {
        const int x = r * 256 + tid;
        cp16(sb + x * 16, (const void*)(H0 + x));
    }
    cp_commit();

    const int* grow = graph + (size_t)(b * Vv + i) * Vv + j0;
    int c0 = 0, c1 = 0;
#pragma unroll
    for (int g = 0; g < 4; g++) {
        const int j = g * 32 + hq;
        const bool un = (grow[j] == 0);
        const unsigned m = __ballot_sync(0xffffffffu, un);
        const int rank = __popc(m & ((1u << hq) - 1u));
        if (g < 2) {
            if (un) jl0[isub][c0 + rank] = j;
            c0 += __popc(m);
        } else {
            if (un) jl1[isub][c1 + rank] = j - 64;
            c1 += __popc(m);
        }
    }

    asm volatile("cp.async.wait_group 0;");
    __syncthreads();

    const float4* Ep = (const float4*)e + ((size_t)(b * Vv + i) * Vv + j0) * H4 + hq;
    const float NEG_INF = __int_as_float(0xff800000);
    float4 acc = make_float4(NEG_INF, NEG_INF, NEG_INF, NEG_INF);

    // ---- mega-chunk 0 ----
    {
        const int* jl = jl0[isub];
        int t = 0;
        for (; t + 4 <= c0; t += 4) {
            int4 j4 = *(const int4*)&jl[t];          // aligned LDS.128
            float4 e0 = __ldcs(&Ep[(size_t)j4.x * H4]);
            float4 e1 = __ldcs(&Ep[(size_t)j4.y * H4]);
            float4 e2 = __ldcs(&Ep[(size_t)j4.z * H4]);
            float4 e3 = __ldcs(&Ep[(size_t)j4.w * H4]);
            float4 h0v = h0s[j4.x * H4 + hq];
            float4 h1v = h0s[j4.y * H4 + hq];
            float4 h2v = h0s[j4.z * H4 + hq];
            float4 h3v = h0s[j4.w * H4 + hq];
            acc.x = fmaxf(acc.x, e0.x * h0v.x); acc.y = fmaxf(acc.y, e0.y * h0v.y);
            acc.z = fmaxf(acc.z, e0.z * h0v.z); acc.w = fmaxf(acc.w, e0.w * h0v.w);
            acc.x = fmaxf(acc.x, e1.x * h1v.x); acc.y = fmaxf(acc.y, e1.y * h1v.y);
            acc.z = fmaxf(acc.z, e1.z * h1v.z); acc.w = fmaxf(acc.w, e1.w * h1v.w);
            acc.x = fmaxf(acc.x, e2.x * h2v.x); acc.y = fmaxf(acc.y, e2.y * h2v.y);
            acc.z = fmaxf(acc.z, e2.z * h2v.z); acc.w = fmaxf(acc.w, e2.w * h2v.w);
            acc.x = fmaxf(acc.x, e3.x * h3v.x); acc.y = fmaxf(acc.y, e3.y * h3v.y);
            acc.z = fmaxf(acc.z, e3.z * h3v.z); acc.w = fmaxf(acc.w, e3.w * h3v.w);
        }
        for (; t < c0; t++) {
            const int j = jl[t];
            float4 ev = __ldcs(&Ep[(size_t)j * H4]);
            float4 hv = h0s[j * H4 + hq];
            acc.x = fmaxf(acc.x, ev.x * hv.x);
            acc.y = fmaxf(acc.y, ev.y * hv.y);
            acc.z = fmaxf(acc.z, ev.z * hv.z);
            acc.w = fmaxf(acc.w, ev.w * hv.w);
        }
    }

    // ---- restage buffer with mega-chunk 1 (j 64..127) ----
    __syncthreads();
#pragma unroll
    for (int r = 0; r < 8; r++) {
        const int x = r * 256 + tid;
        cp16(sb + x * 16, (const void*)(H0 + 2048 + x));
    }
    cp_commit();
    asm volatile("cp.async.wait_group 0;");
    __syncthreads();

    // ---- mega-chunk 1 ----
    {
        const float4* Ep1 = Ep + 64 * H4;
        const int* jl = jl1[isub];
        int t = 0;
        for (; t + 4 <= c1; t += 4) {
            int4 j4 = *(const int4*)&jl[t];
            float4 e0 = __ldcs(&Ep1[(size_t)j4.x * H4]);
            float4 e1 = __ldcs(&Ep1[(size_t)j4.y * H4]);
            float4 e2 = __ldcs(&Ep1[(size_t)j4.z * H4]);
            float4 e3 = __ldcs(&Ep1[(size_t)j4.w * H4]);
            float4 h0v = h0s[j4.x * H4 + hq];
            float4 h1v = h0s[j4.y * H4 + hq];
            float4 h2v = h0s[j4.z * H4 + hq];
            float4 h3v = h0s[j4.w * H4 + hq];
            acc.x = fmaxf(acc.x, e0.x * h0v.x); acc.y = fmaxf(acc.y, e0.y * h0v.y);
            acc.z = fmaxf(acc.z, e0.z * h0v.z); acc.w = fmaxf(acc.w, e0.w * h0v.w);
            acc.x = fmaxf(acc.x, e1.x * h1v.x); acc.y = fmaxf(acc.y, e1.y * h1v.y);
            acc.z = fmaxf(acc.z, e1.z * h1v.z); acc.w = fmaxf(acc.w, e1.w * h1v.w);
            acc.x = fmaxf(acc.x, e2.x * h2v.x); acc.y = fmaxf(acc.y, e2.y * h2v.y);
            acc.z = fmaxf(acc.z, e2.z * h2v.z); acc.w = fmaxf(acc.w, e2.w * h2v.w);
            acc.x = fmaxf(acc.x, e3.x * h3v.x); acc.y = fmaxf(acc.y, e3.y * h3v.y);
            acc.z = fmaxf(acc.z, e3.z * h3v.z); acc.w = fmaxf(acc.w, e3.w * h3v.w);
        }
        for (; t < c1; t++) {
            const int j = jl[t];
            float4 ev = __ldcs(&Ep1[(size_t)j * H4]);
            float4 hv = h0s[j * H4 + hq];
            acc.x = fmaxf(acc.x, ev.x * hv.x);
            acc.y = fmaxf(acc.y, ev.y * hv.y);
            acc.z = fmaxf(acc.z, ev.z * hv.z);
            acc.w = fmaxf(acc.w, ev.w * hv.w);
        }
    }

    if (c0 + c1 < 128) {                  // masked rows contribute exactly 0
        acc.x = fmaxf(acc.x, 0.0f);
        acc.y = fmaxf(acc.y, 0.0f);
        acc.z = fmaxf(acc.z, 0.0f);
        acc.w = fmaxf(acc.w, 0.0f);
    }

    ((float4*)g_part)[((size_t)jh * ROWS + b * Vv + i) * H4 + hq] = acc;
}

// ---------------------------------------------------------------------------
// Kernel C: out = silu( sk + silu([h0,neigh] @ W_post + b_post) )
// 2-D tiled: 512 blocks x 128 threads. v2: W_post in smem as k-pairs;
// inner loop covers 4 k's per iteration with 8 independent FFMA2 chains.
// ---------------------------------------------------------------------------
extern __shared__ float s_dyn[];

__global__ void __launch_bounds__(128) post_kernel(
    const float* __restrict__ Wpost, const float* __restrict__ bpost,
    float* __restrict__ out)
{
    float* sW = s_dyn;                    // pair layout: [(k>>1)][c][k&1], 256x32
    float* aT = s_dyn + 2 * Hv * 32;      // aT[k][r], 256 x 16

    const int tid  = threadIdx.x;
    const int c    = tid & 31;
    const int rg   = tid >> 5;            // 0..3
    const int rowT = blockIdx.x >> 2;
    const int colT = blockIdx.x & 3;
    const int row0 = rowT * 16;
    const int col0 = colT * 32;

    // Stage W slice into pair layout: 16 LDG.128/thread, scatter stores.
    const float4* Wg = (const float4*)Wpost;
#pragma unroll
    for (int r = 0; r < 16; r++) {
        const int x  = r * 128 + tid;          // x = k*8 + c4
        const int k  = x >> 3;
        const int c4 = x & 7;
        float4 v = Wg[k * 32 + colT * 8 + c4];
        const int base = (k >> 1) * 64 + (k & 1);
        sW[base + 2 * (c4 * 4 + 0)] = v.x;
        sW[base + 2 * (c4 * 4 + 1)] = v.y;
        sW[base + 2 * (c4 * 4 + 2)] = v.z;
        sW[base + 2 * (c4 * 4 + 3)] = v.w;
    }

    // Stage transposed h0 and neigh: 512 float4 paths, 4/thread each.
    const float4* h04 = (const float4*)g_h0;
    const float4* gp  = (const float4*)g_part;
#pragma unroll
    for (int x = tid; x < 512; x += 128) {
        const int rr = x & 15, k4 = x >> 4;
        float4 v = h04[(row0 + rr) * H4 + k4];
        aT[(k4 * 4 + 0) * 16 + rr] = v.x;
        aT[(k4 * 4 + 1) * 16 + rr] = v.y;
        aT[(k4 * 4 + 2) * 16 + rr] = v.z;
        aT[(k4 * 4 + 3) * 16 + rr] = v.w;
        float4 p0 = gp[(row0 + rr) * H4 + k4];
        float4 p1 = gp[(size_t)ROWS * H4 + (row0 + rr) * H4 + k4];
        aT[(Hv + k4 * 4 + 0) * 16 + rr] = fmaxf(p0.x, p1.x);
        aT[(Hv + k4 * 4 + 1) * 16 + rr] = fmaxf(p0.y, p1.y);
        aT[(Hv + k4 * 4 + 2) * 16 + rr] = fmaxf(p0.z, p1.z);
        aT[(Hv + k4 * 4 + 3) * 16 + rr] = fmaxf(p0.w, p1.w);
    }
    __syncthreads();

    ull a0, a1, a2, a3, a4, a5, a6, a7;
    {
        const float bP = bpost[col0 + c];
        a0 = pack2(bP, bP); a1 = a0;
        a2 = 0ull; a3 = 0ull; a4 = 0ull; a5 = 0ull; a6 = 0ull; a7 = 0ull;
    }

#pragma unroll 8
    for (int k4i = 0; k4i < (2 * Hv) / 4; k4i++) {
        const int kb = 4 * k4i;
        float2 w01 = *(const float2*)&sW[(2 * k4i + 0) * 64 + 2 * c];  // k kb, kb+1
        float2 w23 = *(const float2*)&sW[(2 * k4i + 1) * 64 + 2 * c];  // k kb+2, kb+3
        ulonglong2 v0 = *(const ulonglong2*)&aT[(kb + 0) * 16 + 4 * rg];
        ulonglong2 v1 = *(const ulonglong2*)&aT[(kb + 1) * 16 + 4 * rg];
        ulonglong2 v2 = *(const ulonglong2*)&aT[(kb + 2) * 16 + 4 * rg];
        ulonglong2 v3 = *(const ulonglong2*)&aT[(kb + 3) * 16 + 4 * rg];
        const ull w0 = pack2(w01.x, w01.x);
        const ull w1 = pack2(w01.y, w01.y);
        const ull w2 = pack2(w23.x, w23.x);
        const ull w3 = pack2(w23.y, w23.y);
        a0 = ffma2(v0.x, w0, a0);
        a1 = ffma2(v0.y, w0, a1);
        a2 = ffma2(v1.x, w1, a2);
        a3 = ffma2(v1.y, w1, a3);
        a4 = ffma2(v2.x, w2, a4);
        a5 = ffma2(v2.y, w2, a5);
        a6 = ffma2(v3.x, w3, a6);
        a7 = ffma2(v3.y, w3, a7);
    }

    {
        float2 u0 = unpack2(a0), u1 = unpack2(a1), u2 = unpack2(a2), u3 = unpack2(a3);
        float2 u4 = unpack2(a4), u5 = unpack2(a5), u6 = unpack2(a6), u7 = unpack2(a7);
        const float r01a = u0.x + u2.x + u4.x + u6.x;   // rows 0-1 of group
        const float r01b = u0.y + u2.y + u4.y + u6.y;
        const float r23a = u1.x + u3.x + u5.x + u7.x;   // rows 2-3 of group
        const float r23b = u1.y + u3.y + u5.y + u7.y;
        const int row = row0 + 4 * rg;
        const int col = col0 + c;
        out[(row + 0) * Hv + col] = silu_f(g_sk[(row + 0) * Hv + col] + silu_f(r01a));
        out[(row + 1) * Hv + col] = silu_f(g_sk[(row + 1) * Hv + col] + silu_f(r01b));
        out[(row + 2) * Hv + col] = silu_f(g_sk[(row + 2) * Hv + col] + silu_f(r23a));
        out[(row + 3) * Hv + col] = silu_f(g_sk[(row + 3) * Hv + col] + silu_f(r23b));
    }
}

// ---------------------------------------------------------------------------
extern "C" void kernel_launch(void* const* d_in, const int* in_sizes, int n_in,
                              void* d_out, int out_size)
{
    const float* h     = (const float*)d_in[0];
    const float* e     = (const float*)d_in[1];
    const int*   graph = (const int*)  d_in[2];
    const float* Wpre  = (const float*)d_in[3];
    const float* bpre  = (const float*)d_in[4];
    const float* Wpost = (const float*)d_in[5];
    const float* bpost = (const float*)d_in[6];
    const float* Wskip = (const float*)d_in[7];
    const float* bskip = (const float*)d_in[8];
    float* out = (float*)d_out;

    const int postSmem = (2 * Hv * 32 + 2 * Hv * 16) * 4;     // 48 KB
    cudaFuncSetAttribute(post_kernel, cudaFuncAttributeMaxDynamicSharedMemorySize, postSmem);

    nop_kernel<<<1, 32>>>();   // keeps ncu's sampled launch on post_kernel
    pre_kernel<<<512, 128>>>(h, Wpre, bpre, Wskip, bskip);
    agg_kernel<<<(ROWS / 8) * 2, 256>>>(e, graph);
    post_kernel<<<512, 128, postSmem>>>(Wpost, bpost, out);
}

// round 15
// speedup vs baseline: 1.0705x; 1.0705x over previous
#include <cuda_runtime.h>
#include <cstdint>

// Problem constants
#define Bv 8
#define Vv 256
#define Hv 128
#define ROWS (Bv*Vv)          // 2048
#define H4 (Hv/4)             // 32 float4 per row

typedef unsigned long long ull;

// Intermediates (device globals; no allocation allowed)
__device__ float g_h0[ROWS*Hv];                 // silu(h @ W_pre + b_pre)
__device__ float g_sk[ROWS*Hv];                 // silu(h @ W_skip + b_skip)
__device__ float g_part[2*ROWS*Hv];             // neigh partial maxes (2 j-halves)

__device__ __forceinline__ float silu_f(float x) {
    return x * (1.0f / (1.0f + __expf(-x)));
}

__device__ __forceinline__ void cp16(uint32_t dst, const void* src) {
    asm volatile("cp.async.cg.shared.global [%0], [%1], 16;" :: "r"(dst), "l"(src));
}
__device__ __forceinline__ void cp_commit() {
    asm volatile("cp.async.commit_group;");
}

__device__ __forceinline__ ull ffma2(ull a, ull b, ull c) {
    ull d;
    asm("fma.rn.f32x2 %0, %1, %2, %3;" : "=l"(d) : "l"(a), "l"(b), "l"(c));
    return d;
}
__device__ __forceinline__ ull add2(ull a, ull b) {
    ull d;
    asm("add.rn.f32x2 %0, %1, %2;" : "=l"(d) : "l"(a), "l"(b));
    return d;
}
__device__ __forceinline__ ull pack2(float x, float y) {
    ull d; asm("mov.b64 %0, {%1, %2};" : "=l"(d) : "f"(x), "f"(y)); return d;
}
__device__ __forceinline__ float2 unpack2(ull v) {
    float2 r; asm("mov.b64 {%0, %1}, %2;" : "=f"(r.x), "=f"(r.y) : "l"(v)); return r;
}

// ---------------------------------------------------------------------------
// No-op kernel: keeps ncu's sampled launch on post_kernel (evidence slot).
// ---------------------------------------------------------------------------
__global__ void nop_kernel() {}

// ---------------------------------------------------------------------------
// Kernel A: h0 = silu(h @ W_pre + b_pre), sk = silu(h @ W_skip + b_skip)
// v3 SPLIT-K: 512 blocks x 256 threads. Block tile = 16 rows x 32 cols.
// Warps 0-3 take k[0,64), warps 4-7 take k[64,128); partials combined via a
// 4 KB smem buffer + packed f32x2 adds. Same smem W/act layout as R12 (the
// 51.9 baseline) -> same LDS wavefront count, but 2x the warps per SM.
// ---------------------------------------------------------------------------
__global__ void __launch_bounds__(256) pre_kernel(
    const float* __restrict__ h,
    const float* __restrict__ Wpre,  const float* __restrict__ bpre,
    const float* __restrict__ Wskip, const float* __restrict__ bskip)
{
    __shared__ float sWA[Hv * 32];       // 16 KB : sWA[k][c]
    __shared__ float sWB[Hv * 32];       // 16 KB
    __shared__ float hT[Hv * 16];        // 8 KB  : hT[k][r]
    __shared__ ull   red[128 * 4];       // 4 KB  : split-K partials

    const int tid  = threadIdx.x;
    const int c    = tid & 31;
    const int rg   = (tid >> 5) & 3;     // 0..3 (4-row group)
    const int kh   = tid >> 7;           // 0/1: k-half
    const int rowT = blockIdx.x >> 2;
    const int colT = blockIdx.x & 3;
    const int row0 = rowT * 16;
    const int col0 = colT * 32;

    // Stage W slices: 1024 float4 each, 4/thread each.
    const float4* WAg = (const float4*)Wpre;
    const float4* WBg = (const float4*)Wskip;
#pragma unroll
    for (int r = 0; r < 4; r++) {
        const int x = r * 256 + tid;           // x = k*8 + c4
        const int src = (x >> 3) * 32 + colT * 8 + (x & 7);
        ((float4*)sWA)[x] = WAg[src];
        ((float4*)sWB)[x] = WBg[src];
    }

    // Stage transposed h rows: 512 float4, 2/thread.
    const float4* h4 = (const float4*)h;
#pragma unroll
    for (int x = tid; x < 512; x += 256) {
        const int rr = x & 15, k4 = x >> 4;
        float4 v = h4[(row0 + rr) * H4 + k4];
        hT[(k4 * 4 + 0) * 16 + rr] = v.x;
        hT[(k4 * 4 + 1) * 16 + rr] = v.y;
        hT[(k4 * 4 + 2) * 16 + rr] = v.z;
        hT[(k4 * 4 + 3) * 16 + rr] = v.w;
    }
    __syncthreads();

    ull aA0, aA1, aB0, aB1;
    if (kh == 0) {
        const float bA = bpre[col0 + c], bB = bskip[col0 + c];
        aA0 = pack2(bA, bA); aA1 = aA0;
        aB0 = pack2(bB, bB); aB1 = aB0;
    } else {
        aA0 = 0ull; aA1 = 0ull; aB0 = 0ull; aB1 = 0ull;
    }

    const int kbeg = kh * 64;
#pragma unroll 16
    for (int kk = 0; kk < 64; kk++) {
        const int k = kbeg + kk;
        ulonglong2 hv = *(const ulonglong2*)&hT[k * 16 + 4 * rg];  // 4 rows, bcast
        const float wa = sWA[k * 32 + c];
        const float wb = sWB[k * 32 + c];
        const ull wa2 = pack2(wa, wa);
        const ull wb2 = pack2(wb, wb);
        aA0 = ffma2(hv.x, wa2, aA0);
        aA1 = ffma2(hv.y, wa2, aA1);
        aB0 = ffma2(hv.x, wb2, aB0);
        aB1 = ffma2(hv.y, wb2, aB1);
    }

    // Split-K combine.
    if (kh == 1) {
        const int s = (tid & 127) * 4;
        red[s + 0] = aA0; red[s + 1] = aA1;
        red[s + 2] = aB0; red[s + 3] = aB1;
    }
    __syncthreads();
    if (kh == 0) {
        const int s = tid * 4;
        aA0 = add2(aA0, red[s + 0]);
        aA1 = add2(aA1, red[s + 1]);
        aB0 = add2(aB0, red[s + 2]);
        aB1 = add2(aB1, red[s + 3]);

        float2 a0 = unpack2(aA0), a1 = unpack2(aA1);
        float2 b0 = unpack2(aB0), b1 = unpack2(aB1);
        const int row = row0 + 4 * rg;
        const int col = col0 + c;
        g_h0[(row + 0) * Hv + col] = silu_f(a0.x);
        g_h0[(row + 1) * Hv + col] = silu_f(a0.y);
        g_h0[(row + 2) * Hv + col] = silu_f(a1.x);
        g_h0[(row + 3) * Hv + col] = silu_f(a1.y);
        g_sk[(row + 0) * Hv + col] = silu_f(b0.x);
        g_sk[(row + 1) * Hv + col] = silu_f(b0.y);
        g_sk[(row + 2) * Hv + col] = silu_f(b1.x);
        g_sk[(row + 3) * Hv + col] = silu_f(b1.y);
    }
}

// ---------------------------------------------------------------------------
// Kernel B (dominant): partial neigh max over a 128-wide j-half. (frozen R12)
// ---------------------------------------------------------------------------
__global__ void __launch_bounds__(256) agg_kernel(
    const float* __restrict__ e,
    const int*   __restrict__ graph)
{
    __shared__ float4 h0s[64 * H4];      // 32 KB : h0s[jj][hq], jj in [0,64)
    __shared__ int    jl0[8][64];        // 2 KB  : unmasked j in [0,64)
    __shared__ int    jl1[8][64];        // 2 KB  : unmasked j in [64,128)

    const int tid  = threadIdx.x;
    const int hq   = tid & 31;           // float4 index in H == lane
    const int isub = tid >> 5;           // 0..7 == warp index
    const int b    = blockIdx.x >> 6;
    const int rem  = blockIdx.x & 63;
    const int i0   = (rem >> 1) * 8;
    const int jh   = rem & 1;
    const int j0   = jh * 128;
    const int i    = i0 + isub;

    const float4* H0 = (const float4*)g_h0 + (b * Vv + j0) * H4;
    const uint32_t sb = (uint32_t)__cvta_generic_to_shared(&h0s[0]);

#pragma unroll
    for (int r = 0; r < 8; r++) {
        const int x = r * 256 + tid;
        cp16(sb + x * 16, (const void*)(H0 + x));
    }
    cp_commit();

    const int* grow = graph + (size_t)(b * Vv + i) * Vv + j0;
    int c0 = 0, c1 = 0;
#pragma unroll
    for (int g = 0; g < 4; g++) {
        const int j = g * 32 + hq;
        const bool un = (grow[j] == 0);
        const unsigned m = __ballot_sync(0xffffffffu, un);
        const int rank = __popc(m & ((1u << hq) - 1u));
        if (g < 2) {
            if (un) jl0[isub][c0 + rank] = j;
            c0 += __popc(m);
        } else {
            if (un) jl1[isub][c1 + rank] = j - 64;
            c1 += __popc(m);
        }
    }

    asm volatile("cp.async.wait_group 0;");
    __syncthreads();

    const float4* Ep = (const float4*)e + ((size_t)(b * Vv + i) * Vv + j0) * H4 + hq;
    const float NEG_INF = __int_as_float(0xff800000);
    float4 acc = make_float4(NEG_INF, NEG_INF, NEG_INF, NEG_INF);

    // ---- mega-chunk 0 ----
    {
        const int* jl = jl0[isub];
        int t = 0;
        for (; t + 4 <= c0; t += 4) {
            int4 j4 = *(const int4*)&jl[t];          // aligned LDS.128
            float4 e0 = __ldcs(&Ep[(size_t)j4.x * H4]);
            float4 e1 = __ldcs(&Ep[(size_t)j4.y * H4]);
            float4 e2 = __ldcs(&Ep[(size_t)j4.z * H4]);
            float4 e3 = __ldcs(&Ep[(size_t)j4.w * H4]);
            float4 h0v = h0s[j4.x * H4 + hq];
            float4 h1v = h0s[j4.y * H4 + hq];
            float4 h2v = h0s[j4.z * H4 + hq];
            float4 h3v = h0s[j4.w * H4 + hq];
            acc.x = fmaxf(acc.x, e0.x * h0v.x); acc.y = fmaxf(acc.y, e0.y * h0v.y);
            acc.z = fmaxf(acc.z, e0.z * h0v.z); acc.w = fmaxf(acc.w, e0.w * h0v.w);
            acc.x = fmaxf(acc.x, e1.x * h1v.x); acc.y = fmaxf(acc.y, e1.y * h1v.y);
            acc.z = fmaxf(acc.z, e1.z * h1v.z); acc.w = fmaxf(acc.w, e1.w * h1v.w);
            acc.x = fmaxf(acc.x, e2.x * h2v.x); acc.y = fmaxf(acc.y, e2.y * h2v.y);
            acc.z = fmaxf(acc.z, e2.z * h2v.z); acc.w = fmaxf(acc.w, e2.w * h2v.w);
            acc.x = fmaxf(acc.x, e3.x * h3v.x); acc.y = fmaxf(acc.y, e3.y * h3v.y);
            acc.z = fmaxf(acc.z, e3.z * h3v.z); acc.w = fmaxf(acc.w, e3.w * h3v.w);
        }
        for (; t < c0; t++) {
            const int j = jl[t];
            float4 ev = __ldcs(&Ep[(size_t)j * H4]);
            float4 hv = h0s[j * H4 + hq];
            acc.x = fmaxf(acc.x, ev.x * hv.x);
            acc.y = fmaxf(acc.y, ev.y * hv.y);
            acc.z = fmaxf(acc.z, ev.z * hv.z);
            acc.w = fmaxf(acc.w, ev.w * hv.w);
        }
    }

    // ---- restage buffer with mega-chunk 1 (j 64..127) ----
    __syncthreads();
#pragma unroll
    for (int r = 0; r < 8; r++) {
        const int x = r * 256 + tid;
        cp16(sb + x * 16, (const void*)(H0 + 2048 + x));
    }
    cp_commit();
    asm volatile("cp.async.wait_group 0;");
    __syncthreads();

    // ---- mega-chunk 1 ----
    {
        const float4* Ep1 = Ep + 64 * H4;
        const int* jl = jl1[isub];
        int t = 0;
        for (; t + 4 <= c1; t += 4) {
            int4 j4 = *(const int4*)&jl[t];
            float4 e0 = __ldcs(&Ep1[(size_t)j4.x * H4]);
            float4 e1 = __ldcs(&Ep1[(size_t)j4.y * H4]);
            float4 e2 = __ldcs(&Ep1[(size_t)j4.z * H4]);
            float4 e3 = __ldcs(&Ep1[(size_t)j4.w * H4]);
            float4 h0v = h0s[j4.x * H4 + hq];
            float4 h1v = h0s[j4.y * H4 + hq];
            float4 h2v = h0s[j4.z * H4 + hq];
            float4 h3v = h0s[j4.w * H4 + hq];
            acc.x = fmaxf(acc.x, e0.x * h0v.x); acc.y = fmaxf(acc.y, e0.y * h0v.y);
            acc.z = fmaxf(acc.z, e0.z * h0v.z); acc.w = fmaxf(acc.w, e0.w * h0v.w);
            acc.x = fmaxf(acc.x, e1.x * h1v.x); acc.y = fmaxf(acc.y, e1.y * h1v.y);
            acc.z = fmaxf(acc.z, e1.z * h1v.z); acc.w = fmaxf(acc.w, e1.w * h1v.w);
            acc.x = fmaxf(acc.x, e2.x * h2v.x); acc.y = fmaxf(acc.y, e2.y * h2v.y);
            acc.z = fmaxf(acc.z, e2.z * h2v.z); acc.w = fmaxf(acc.w, e2.w * h2v.w);
            acc.x = fmaxf(acc.x, e3.x * h3v.x); acc.y = fmaxf(acc.y, e3.y * h3v.y);
            acc.z = fmaxf(acc.z, e3.z * h3v.z); acc.w = fmaxf(acc.w, e3.w * h3v.w);
        }
        for (; t < c1; t++) {
            const int j = jl[t];
            float4 ev = __ldcs(&Ep1[(size_t)j * H4]);
            float4 hv = h0s[j * H4 + hq];
            acc.x = fmaxf(acc.x, ev.x * hv.x);
            acc.y = fmaxf(acc.y, ev.y * hv.y);
            acc.z = fmaxf(acc.z, ev.z * hv.z);
            acc.w = fmaxf(acc.w, ev.w * hv.w);
        }
    }

    if (c0 + c1 < 128) {                  // masked rows contribute exactly 0
        acc.x = fmaxf(acc.x, 0.0f);
        acc.y = fmaxf(acc.y, 0.0f);
        acc.z = fmaxf(acc.z, 0.0f);
        acc.w = fmaxf(acc.w, 0.0f);
    }

    ((float4*)g_part)[((size_t)jh * ROWS + b * Vv + i) * H4 + hq] = acc;
}

// ---------------------------------------------------------------------------
// Kernel C: out = silu( sk + silu([h0,neigh] @ W_post + b_post) )
// v3 SPLIT-K: 512 blocks x 256 threads. Warps 0-3 take k[0,128), warps 4-7
// take k[128,256); 2 KB smem reduction. W/aT layout identical to R12/R13.
// Dynamic smem: [sW 256*32][aT 256*16][red 128*2 ull] = 50 KB.
// ---------------------------------------------------------------------------
extern __shared__ float s_dyn[];

__global__ void __launch_bounds__(256) post_kernel(
    const float* __restrict__ Wpost, const float* __restrict__ bpost,
    float* __restrict__ out)
{
    float* sW = s_dyn;                    // sW[k][c], 256 x 32
    float* aT = s_dyn + 2 * Hv * 32;      // aT[k][r], 256 x 16
    ull*   red = (ull*)(s_dyn + 2 * Hv * 32 + 2 * Hv * 16);  // 128 x 2

    const int tid  = threadIdx.x;
    const int c    = tid & 31;
    const int rg   = (tid >> 5) & 3;      // 0..3
    const int kh   = tid >> 7;            // 0/1: k-half
    const int rowT = blockIdx.x >> 2;
    const int colT = blockIdx.x & 3;
    const int row0 = rowT * 16;
    const int col0 = colT * 32;

    // Stage W slice: 2048 float4, 8/thread.
    const float4* Wg = (const float4*)Wpost;
#pragma unroll
    for (int r = 0; r < 8; r++) {
        const int x = r * 256 + tid;           // x = k*8 + c4
        ((float4*)sW)[x] = Wg[(x >> 3) * 32 + colT * 8 + (x & 7)];
    }

    // Stage transposed h0 and neigh: 512 float4 paths, 2/thread each.
    const float4* h04 = (const float4*)g_h0;
    const float4* gp  = (const float4*)g_part;
#pragma unroll
    for (int x = tid; x < 512; x += 256) {
        const int rr = x & 15, k4 = x >> 4;
        float4 v = h04[(row0 + rr) * H4 + k4];
        aT[(k4 * 4 + 0) * 16 + rr] = v.x;
        aT[(k4 * 4 + 1) * 16 + rr] = v.y;
        aT[(k4 * 4 + 2) * 16 + rr] = v.z;
        aT[(k4 * 4 + 3) * 16 + rr] = v.w;
        float4 p0 = gp[(row0 + rr) * H4 + k4];
        float4 p1 = gp[(size_t)ROWS * H4 + (row0 + rr) * H4 + k4];
        aT[(Hv + k4 * 4 + 0) * 16 + rr] = fmaxf(p0.x, p1.x);
        aT[(Hv + k4 * 4 + 1) * 16 + rr] = fmaxf(p0.y, p1.y);
        aT[(Hv + k4 * 4 + 2) * 16 + rr] = fmaxf(p0.z, p1.z);
        aT[(Hv + k4 * 4 + 3) * 16 + rr] = fmaxf(p0.w, p1.w);
    }
    __syncthreads();

    ull acc0, acc1;
    if (kh == 0) {
        const float bP = bpost[col0 + c];
        acc0 = pack2(bP, bP);
        acc1 = 0ull;
    } else {
        acc0 = 0ull; acc1 = 0ull;
    }

    const int kbeg = kh * Hv;
#pragma unroll 16
    for (int kk = 0; kk < Hv; kk++) {
        const int k = kbeg + kk;
        ulonglong2 av = *(const ulonglong2*)&aT[k * 16 + 4 * rg];  // 4 rows, bcast
        const float w = sW[k * 32 + c];
        const ull w2 = pack2(w, w);
        acc0 = ffma2(av.x, w2, acc0);
        acc1 = ffma2(av.y, w2, acc1);
    }

    // Split-K combine.
    if (kh == 1) {
        const int s = (tid & 127) * 2;
        red[s + 0] = acc0;
        red[s + 1] = acc1;
    }
    __syncthreads();
    if (kh == 0) {
        const int s = tid * 2;
        acc0 = add2(acc0, red[s + 0]);
        acc1 = add2(acc1, red[s + 1]);

        float2 v0 = unpack2(acc0), v1 = unpack2(acc1);
        const int row = row0 + 4 * rg;
        const int col = col0 + c;
        out[(row + 0) * Hv + col] = silu_f(g_sk[(row + 0) * Hv + col] + silu_f(v0.x));
        out[(row + 1) * Hv + col] = silu_f(g_sk[(row + 1) * Hv + col] + silu_f(v0.y));
        out[(row + 2) * Hv + col] = silu_f(g_sk[(row + 2) * Hv + col] + silu_f(v1.x));
        out[(row + 3) * Hv + col] = silu_f(g_sk[(row + 3) * Hv + col] + silu_f(v1.y));
    }
}

// ---------------------------------------------------------------------------
extern "C" void kernel_launch(void* const* d_in, const int* in_sizes, int n_in,
                              void* d_out, int out_size)
{
    const float* h     = (const float*)d_in[0];
    const float* e     = (const float*)d_in[1];
    const int*   graph = (const int*)  d_in[2];
    const float* Wpre  = (const float*)d_in[3];
    const float* bpre  = (const float*)d_in[4];
    const float* Wpost = (const float*)d_in[5];
    const float* bpost = (const float*)d_in[6];
    const float* Wskip = (const float*)d_in[7];
    const float* bskip = (const float*)d_in[8];
    float* out = (float*)d_out;

    const int postSmem = (2 * Hv * 32 + 2 * Hv * 16) * 4 + 128 * 2 * 8;  // 50 KB
    cudaFuncSetAttribute(post_kernel, cudaFuncAttributeMaxDynamicSharedMemorySize, postSmem);

    nop_kernel<<<1, 32>>>();   // keeps ncu's sampled launch on post_kernel
    pre_kernel<<<512, 256>>>(h, Wpre, bpre, Wskip, bskip);
    agg_kernel<<<(ROWS / 8) * 2, 256>>>(e, graph);
    post_kernel<<<512, 256, postSmem>>>(Wpost, bpost, out);
}